// round 1
// baseline (speedup 1.0000x reference)
#include <cuda_runtime.h>
#include <math.h>

#define T_STEPS 4096
#define BATCH   128
#define IN_DIM  96
#define H_DIM   64
#define OUT_DIM 2

// Precomputed input currents: P[t][b][h] = (t==0 ? 0 : x[t-1,b,:] @ W_h[h,:])
__device__ float g_P[(size_t)T_STEPS * BATCH * H_DIM];

// ---------- packed f32x2 helpers ----------
__device__ __forceinline__ void fma2(unsigned long long& d, unsigned long long a, unsigned long long b) {
    asm("fma.rn.f32x2 %0, %1, %2, %0;" : "+l"(d) : "l"(a), "l"(b));
}
__device__ __forceinline__ unsigned long long add2(unsigned long long a, unsigned long long b) {
    unsigned long long d;
    asm("add.rn.f32x2 %0, %1, %2;" : "=l"(d) : "l"(a), "l"(b));
    return d;
}
__device__ __forceinline__ unsigned long long pack2(float x, float y) {
    unsigned long long r;
    asm("mov.b64 %0, {%1, %2};" : "=l"(r) : "f"(x), "f"(y));
    return r;
}
__device__ __forceinline__ float lo32(unsigned long long v) { return __uint_as_float((unsigned)v); }
__device__ __forceinline__ float hi32(unsigned long long v) { return __uint_as_float((unsigned)(v >> 32)); }

// ============================================================
// Kernel 1: P[g] = (g >= BATCH) ? x[g-BATCH,:] @ W_h.T : 0
// rows g = t*BATCH + b, total T*B rows. Tile: 32 rows x 64 cols per CTA.
// ============================================================
__global__ __launch_bounds__(256) void precompute_inp(const float* __restrict__ x,
                                                      const float* __restrict__ Wh) {
    __shared__ unsigned long long xp[48][34];  // [k-pair][row], padded stride (even)
    __shared__ unsigned long long wp[48][66];  // [k-pair][col], padded stride (even)

    const int tid = threadIdx.x;
    const long long row0 = (long long)blockIdx.x * 32;

    // Fill W pairs: wp[kk][c] = (Wh[c][2kk], Wh[c][2kk+1])
    for (int l = tid; l < H_DIM * 48; l += 256) {
        int c = l / 48, kk = l % 48;
        float2 w2 = ((const float2*)(Wh + (size_t)c * IN_DIM))[kk];
        wp[kk][c] = pack2(w2.x, w2.y);
    }
    // Fill x pairs with the 1-step shift (t==0 rows -> zeros)
    for (int l = tid; l < 32 * 48; l += 256) {
        int r = l / 48, kk = l % 48;
        long long g = row0 + r;
        float2 v2 = make_float2(0.f, 0.f);
        if (g >= BATCH) v2 = ((const float2*)(x + (g - BATCH) * IN_DIM))[kk];
        xp[kk][r] = pack2(v2.x, v2.y);
    }
    __syncthreads();

    const int tx = tid & 15, ty = tid >> 4;
    const int r0 = ty * 2, c0 = tx * 4;

    unsigned long long acc[2][4];
#pragma unroll
    for (int i = 0; i < 2; i++)
#pragma unroll
        for (int j = 0; j < 4; j++) acc[i][j] = 0ull;

#pragma unroll
    for (int kk = 0; kk < 48; kk++) {
        ulonglong2 a  = *(const ulonglong2*)&xp[kk][r0];
        ulonglong2 b0 = *(const ulonglong2*)&wp[kk][c0];
        ulonglong2 b1 = *(const ulonglong2*)&wp[kk][c0 + 2];
        fma2(acc[0][0], a.x, b0.x); fma2(acc[0][1], a.x, b0.y);
        fma2(acc[0][2], a.x, b1.x); fma2(acc[0][3], a.x, b1.y);
        fma2(acc[1][0], a.y, b0.x); fma2(acc[1][1], a.y, b0.y);
        fma2(acc[1][2], a.y, b1.x); fma2(acc[1][3], a.y, b1.y);
    }

#pragma unroll
    for (int i = 0; i < 2; i++) {
        float4 o;
        o.x = lo32(acc[i][0]) + hi32(acc[i][0]);
        o.y = lo32(acc[i][1]) + hi32(acc[i][1]);
        o.z = lo32(acc[i][2]) + hi32(acc[i][2]);
        o.w = lo32(acc[i][3]) + hi32(acc[i][3]);
        *(float4*)(g_P + (size_t)(row0 + r0 + i) * H_DIM + c0) = o;
    }
}

// ============================================================
// Kernel 2: sequential scan. One CTA per batch, 96 threads:
//   tid 0..63  : hidden neuron i (V row in regs, state syn/mem)
//   tid 64,65  : readout unit (W_o row in regs, state syn_o/mem_o)
//   tid 66..95 : dummy (keeps warp 2 uniform; results discarded)
// Spikes broadcast via double-buffered shared array; 1 barrier/step.
// ============================================================
__global__ __launch_bounds__(96, 1) void scan_kernel(const float* __restrict__ V,
                                                     const float* __restrict__ Wo,
                                                     float* __restrict__ out,
                                                     float a_h, float b_h,
                                                     float a_o, float b_o) {
    __shared__ __align__(16) float spk[2][H_DIM];

    const int b   = blockIdx.x;
    const int tid = threadIdx.x;
    const bool is_n = (tid < H_DIM);
    const bool is_o = (tid >= H_DIM) && (tid < H_DIM + OUT_DIM);

    // Row of weights for my dot product (V row for neurons, W_o row for readout)
    const float* rowp = is_n ? (V + (size_t)tid * H_DIM)
                             : (Wo + (size_t)(is_o ? (tid - H_DIM) : 0) * H_DIM);
    unsigned long long Wp[32];
    {
        const float2* r2 = (const float2*)rowp;
#pragma unroll
        for (int q = 0; q < 32; q++) {
            float2 t = r2[q];
            Wp[q] = pack2(t.x, t.y);
        }
    }

    if (is_n) { spk[0][tid] = 0.f; spk[1][tid] = 0.f; }

    float syn = 0.f, mem = 0.f;   // neuron: (syn,mem); readout: (syn_o,mem_o)
    const float omb_h = 1.f - b_h;
    const float omb_o = 1.f - b_o;

    const int strideP = BATCH * H_DIM;
    const float* p = g_P + (size_t)b * H_DIM + (is_n ? tid : 0);
    float cur[8];
#pragma unroll
    for (int q = 0; q < 8; q++) cur[q] = p[(size_t)q * strideP];
    const float* pf = p + (size_t)8 * strideP;

    float* optr = out + (size_t)b * OUT_DIM + (is_o ? (tid - H_DIM) : 0);

    __syncthreads();

#pragma unroll 8
    for (int t = 0; t < T_STEPS; t++) {
        const int rb = t & 1;

        // dot = sum_j row[j] * spk_prev[j]   (all threads)
        const ulonglong2* sp2 = (const ulonglong2*)(&spk[rb][0]);
        unsigned long long acc0 = 0ull, acc1 = 0ull, acc2 = 0ull, acc3 = 0ull;
#pragma unroll
        for (int q = 0; q < 16; q += 2) {
            ulonglong2 sA = sp2[q];
            ulonglong2 sB = sp2[q + 1];
            fma2(acc0, Wp[2 * q + 0], sA.x);
            fma2(acc1, Wp[2 * q + 1], sA.y);
            fma2(acc2, Wp[2 * q + 2], sB.x);
            fma2(acc3, Wp[2 * q + 3], sB.y);
        }
        unsigned long long accp = add2(add2(acc0, acc1), add2(acc2, acc3));
        const float dot = lo32(accp) + hi32(accp);

        if (is_n) {
            syn = fmaf(a_h, syn, cur[t & 7] + dot);
            if (t + 8 < T_STEPS) cur[t & 7] = *pf;   // prefetch 8 steps ahead
            pf += strideP;
            mem = fmaf(b_h, mem, omb_h * syn);
            float s_ = (mem > 1.f) ? 1.f : 0.f;
            mem = (mem > 1.f) ? 0.f : mem;
            spk[rb ^ 1][tid] = s_;
        } else if (is_o) {
            syn = fmaf(a_o, syn, dot);
            mem = fmaf(b_o, mem, omb_o * syn);
            optr[(size_t)t * (BATCH * OUT_DIM)] = mem;
        }
        __syncthreads();
    }
}

// ============================================================
extern "C" void kernel_launch(void* const* d_in, const int* in_sizes, int n_in,
                              void* d_out, int out_size) {
    const float* x  = (const float*)d_in[0];
    const float* Wh = (const float*)d_in[1];
    const float* V  = (const float*)d_in[2];
    const float* Wo = (const float*)d_in[3];
    float* out = (float*)d_out;

    // decay constants (taus: softplus(1)*{0.01, 0.02}); ratio in double, exp in f32
    const double S = log1p(exp(1.0));
    const float a_h = expf((float)(-0.004 / (S * 0.01)));
    const float b_h = expf((float)(-0.004 / (S * 0.02)));
    const float a_o = a_h;
    const float b_o = b_h;

    precompute_inp<<<(T_STEPS * BATCH) / 32, 256>>>(x, Wh);
    scan_kernel<<<BATCH, 96>>>(V, Wo, out, a_h, b_h, a_o, b_o);
}